// round 7
// baseline (speedup 1.0000x reference)
#include <cuda_runtime.h>
#include <math.h>

#define Nn 64
#define Cc 3
#define Hh 256
#define Ww 256
#define TAP 43
#define PAD 21
#define RY 16   // rows per thread in vertical pass

struct Params {
    float M[12];      // rows 0..2 of the 4x4 color matrix (3x4: 3x3 + bias col)
    float k[TAP];     // per-image separable filter taps
    float sigma, cx, cy, half;
};

__device__ Params g_params[Nn];
// scratch between passes; float4-typed so the base is 16B-aligned for vector access
__device__ float4 g_tmp4[(Nn * Cc * Hh * Ww) / 4];   // 50.3 MB (L2-resident between passes)

typedef unsigned long long u64;

// packed fp32x2 FMA: acc = v * k + acc  (per-lane IEEE f32, PTX ISA sm_100+)
__device__ __forceinline__ void fma2(u64& acc, u64 v, u64 k) {
    asm("fma.rn.f32x2 %0, %1, %2, %3;" : "=l"(acc) : "l"(v), "l"(k), "l"(acc));
}

__device__ __forceinline__ void mm4(const float A[4][4], const float B[4][4], float C[4][4]) {
#pragma unroll
    for (int i = 0; i < 4; ++i)
#pragma unroll
        for (int j = 0; j < 4; ++j)
            C[i][j] = A[i][0]*B[0][j] + A[i][1]*B[1][j] + A[i][2]*B[2][j] + A[i][3]*B[3][j];
}

__global__ void params_kernel(const float* __restrict__ gates,
                              const float* __restrict__ gauss,
                              const float* __restrict__ unif,
                              const float* __restrict__ fbank) {
    int n = threadIdx.x;
    if (n >= Nn) return;
    const float P = 1.0f;
    const float third = 1.0f / 3.0f;

    // ---- color matrix chain: Cm = W @ R4 @ L @ (S @ T) ----
    float b  = (gates[n*11+0] < P) ? gauss[n*8+0] * 0.2f : 0.0f;
    float cc = (gates[n*11+1] < P) ? exp2f(gauss[n*8+1] * 0.5f) : 1.0f;

    float T[4][4] = {{1,0,0,b},{0,1,0,b},{0,0,1,b},{0,0,0,1}};
    float S[4][4] = {{cc,0,0,0},{0,cc,0,0},{0,0,cc,0},{0,0,0,1}};
    float C1[4][4]; mm4(S, T, C1);

    float ilf = floorf(unif[n*4+0] * 2.0f);
    if (!(gates[n*11+2] < P)) ilf = 0.0f;
    float Lm[4][4];
#pragma unroll
    for (int i = 0; i < 4; ++i)
#pragma unroll
        for (int j = 0; j < 4; ++j) {
            float vvij = (i < 3 && j < 3) ? third : 0.0f;
            Lm[i][j] = ((i == j) ? 1.0f : 0.0f) - 2.0f * vvij * ilf;
        }
    float C2[4][4]; mm4(Lm, C1, C2);

    float theta = (gates[n*11+3] < P) ? (unif[n*4+1] * 2.0f - 1.0f) * 3.14159274f : 0.0f;
    float si, co;
    sincosf(theta, &si, &co);
    const float iv = 0.57735026918962576f;
    const float Kk[3][3] = {{0.0f,-iv,iv},{iv,0.0f,-iv},{-iv,iv,0.0f}};
    float R4[4][4] = {{0,0,0,0},{0,0,0,0},{0,0,0,0},{0,0,0,1}};
#pragma unroll
    for (int i = 0; i < 3; ++i)
#pragma unroll
        for (int j = 0; j < 3; ++j)
            R4[i][j] = (1.0f - co) * third + co * ((i == j) ? 1.0f : 0.0f) + si * Kk[i][j];
    float C3[4][4]; mm4(R4, C2, C3);

    float sat = (gates[n*11+4] < P) ? exp2f(gauss[n*8+2]) : 1.0f;
    float Wm[4][4];
#pragma unroll
    for (int i = 0; i < 4; ++i)
#pragma unroll
        for (int j = 0; j < 4; ++j) {
            float vvij = (i < 3 && j < 3) ? third : 0.0f;
            Wm[i][j] = vvij + (((i == j) ? 1.0f : 0.0f) - vvij) * sat;
        }
    float Cm[4][4]; mm4(Wm, C3, Cm);

    Params p;
#pragma unroll
    for (int i = 0; i < 3; ++i)
#pragma unroll
        for (int j = 0; j < 4; ++j)
            p.M[i*4 + j] = Cm[i][j];

    // ---- filter band gains: g = prod_i normalize(t_i) ; k = g @ fbank ----
    float g4[4] = {1.0f, 1.0f, 1.0f, 1.0f};
    const float ep0 = 10.0f / 13.0f, ep1 = 1.0f / 13.0f;
#pragma unroll
    for (int i = 0; i < 4; ++i) {
        float ti = (gates[n*11+5+i] < P) ? exp2f(gauss[n*8+3+i]) : 1.0f;
        float t[4] = {1.0f, 1.0f, 1.0f, 1.0f};
        t[i] = ti;
        float ss = ep0*t[0]*t[0] + ep1*t[1]*t[1] + ep1*t[2]*t[2] + ep1*t[3]*t[3];
        float inv = 1.0f / sqrtf(ss);
#pragma unroll
        for (int j = 0; j < 4; ++j) g4[j] *= t[j] * inv;
    }
#pragma unroll
    for (int tp = 0; tp < TAP; ++tp)
        p.k[tp] = g4[0]*fbank[0*TAP+tp] + g4[1]*fbank[1*TAP+tp]
                + g4[2]*fbank[2*TAP+tp] + g4[3]*fbank[3*TAP+tp];

    p.sigma = (gates[n*11+9] < P) ? fabsf(gauss[n*8+7]) * 0.1f : 0.0f;
    p.cx   = unif[n*4+2];
    p.cy   = unif[n*4+3];
    p.half = (gates[n*11+10] < P) ? 0.25f : 0.0f;
    g_params[n] = p;
}

// ---- pass 1: color transform + horizontal 43-tap conv (reflect pad) ----
// block = (row-pair, n), 192 threads: 3 channels x 64 x-groups.
// Two image rows processed together, interleaved in smem as float2(y0,y1),
// so each packed fma2 produces both rows at once.
__global__ void hpass_kernel(const float* __restrict__ img) {
    int y0 = blockIdx.x * 2, n = blockIdx.y;
    int tid = threadIdx.x;

    __shared__ __align__(16) float2 t2[3][304];  // [channel][pos] -> (row y0, row y1)
    __shared__ float2 ks2[TAP];                  // duplicated taps (k,k)
    __shared__ float  Ms[12];

    if (tid < 12) Ms[tid] = g_params[n].M[tid];
    if (tid >= 64 && tid < 64 + TAP) {
        float kv = g_params[n].k[tid - 64];
        ks2[tid - 64] = make_float2(kv, kv);
    }
    __syncthreads();

    const float* base = img + (size_t)n * 3 * Hh * Ww;

#pragma unroll
    for (int it = 0; it < 2; ++it) {
        int p = tid + it * 192;
        if (p < Ww + 2*PAD) {
            int xr = p - PAD;
            xr = xr < 0 ? -xr : (xr >= Ww ? 2*Ww - 2 - xr : xr);
            float r0 = base[(0*Hh + y0    ) * Ww + xr];
            float g0 = base[(1*Hh + y0    ) * Ww + xr];
            float b0 = base[(2*Hh + y0    ) * Ww + xr];
            float r1 = base[(0*Hh + y0 + 1) * Ww + xr];
            float g1 = base[(1*Hh + y0 + 1) * Ww + xr];
            float b1 = base[(2*Hh + y0 + 1) * Ww + xr];
            t2[0][p] = make_float2(Ms[0]*r0 + Ms[1]*g0 + Ms[2] *b0 + Ms[3],
                                   Ms[0]*r1 + Ms[1]*g1 + Ms[2] *b1 + Ms[3]);
            t2[1][p] = make_float2(Ms[4]*r0 + Ms[5]*g0 + Ms[6] *b0 + Ms[7],
                                   Ms[4]*r1 + Ms[5]*g1 + Ms[6] *b1 + Ms[7]);
            t2[2][p] = make_float2(Ms[8]*r0 + Ms[9]*g0 + Ms[10]*b0 + Ms[11],
                                   Ms[8]*r1 + Ms[9]*g1 + Ms[10]*b1 + Ms[11]);
        }
    }
    __syncthreads();

    int c = tid / 64, xg = tid % 64;           // outputs x0..x0+3, x0 = 4*xg
    const ulonglong2* tv = (const ulonglong2*)&t2[c][0];   // 2 positions per 16B
    const u64* kk = (const u64*)ks2;

    u64 acc[4] = {0ull, 0ull, 0ull, 0ull};
#pragma unroll
    for (int q = 0; q < 24; ++q) {            // covers padded positions x0 .. x0+47
        ulonglong2 v = tv[xg*2 + q];
#pragma unroll
        for (int i = 0; i < 4; ++i) {
            int pp0 = 2*q - i;                // tap index for output x0+i, element 0
            if (pp0 >= 0 && pp0 < TAP) fma2(acc[i], v.x, kk[pp0]);
            int pp1 = 2*q + 1 - i;
            if (pp1 >= 0 && pp1 < TAP) fma2(acc[i], v.y, kk[pp1]);
        }
    }

    float2 a0 = *(float2*)&acc[0], a1 = *(float2*)&acc[1];
    float2 a2 = *(float2*)&acc[2], a3 = *(float2*)&acc[3];
    float* gt = (float*)g_tmp4;
    float* trow0 = gt + ((size_t)(n*3+c)*Hh + y0    ) * Ww + xg*4;
    float* trow1 = gt + ((size_t)(n*3+c)*Hh + y0 + 1) * Ww + xg*4;
    *((float4*)trow0) = make_float4(a0.x, a1.x, a2.x, a3.x);
    *((float4*)trow1) = make_float4(a0.y, a1.y, a2.y, a3.y);
}

// ---- pass 2: vertical 43-tap conv (reflect pad) + noise + cutout mask ----
// block = (ytile, c, n), 128 threads; each thread owns 2 adjacent columns
// (packed float2), RY rows via register sliding window of packed accumulators.
__global__ void vpass_kernel(const float* __restrict__ noise, float* __restrict__ out) {
    int n = blockIdx.z, c = blockIdx.y;
    int y0 = blockIdx.x * RY;
    int x0 = threadIdx.x * 2;

    __shared__ float2 ks2[TAP];
    __shared__ float  sc[4];
    if (threadIdx.x < TAP) {
        float kv = g_params[n].k[threadIdx.x];
        ks2[threadIdx.x] = make_float2(kv, kv);
    }
    if (threadIdx.x == 64) {
        sc[0] = g_params[n].sigma; sc[1] = g_params[n].cx;
        sc[2] = g_params[n].cy;    sc[3] = g_params[n].half;
    }
    __syncthreads();

    const float* base = (const float*)g_tmp4 + (size_t)(n*3+c) * Hh * Ww;
    const u64* kk = (const u64*)ks2;

    u64 acc[RY];
#pragma unroll
    for (int r = 0; r < RY; ++r) acc[r] = 0ull;

#pragma unroll
    for (int tt = 0; tt < RY + 2*PAD; ++tt) {
        int yr = y0 + tt - PAD;
        yr = yr < 0 ? -yr : (yr >= Hh ? 2*Hh - 2 - yr : yr);
        u64 v = *(const u64*)(base + yr * Ww + x0);
#pragma unroll
        for (int r = 0; r < RY; ++r) {
            int j = tt - r;                    // compile-time in unrolled code
            if (j >= 0 && j < TAP) fma2(acc[r], v, kk[j]);
        }
    }

    float sigma = sc[0], cx = sc[1], cy = sc[2], half = sc[3];
    u64 sig2; { float2 s2 = make_float2(sigma, sigma); sig2 = *(u64*)&s2; }
    bool mx0 = fabsf((x0 + 0.5f)     * (1.0f/Ww) - cx) >= half;
    bool mx1 = fabsf((x0 + 1 + 0.5f) * (1.0f/Ww) - cx) >= half;
    const float* nb = noise + (size_t)(n*3+c) * Hh * Ww;
    float* ob = out + (size_t)(n*3+c) * Hh * Ww;
#pragma unroll
    for (int r = 0; r < RY; ++r) {
        int y = y0 + r;
        bool my = fabsf((y + 0.5f) * (1.0f/Hh) - cy) >= half;
        u64 nv = *(const u64*)(nb + y * Ww + x0);
        u64 res = acc[r];
        fma2(res, nv, sig2);                   // res = acc + noise*sigma (packed)
        float2 f = *(float2*)&res;
        float2 o;
        o.x = (mx0 || my) ? f.x : 0.0f;
        o.y = (mx1 || my) ? f.y : 0.0f;
        *((float2*)(ob + y * Ww + x0)) = o;
    }
}

extern "C" void kernel_launch(void* const* d_in, const int* in_sizes, int n_in,
                              void* d_out, int out_size) {
    const float* images = (const float*)d_in[0];
    const float* gates  = (const float*)d_in[1];
    const float* gauss  = (const float*)d_in[2];
    const float* unif   = (const float*)d_in[3];
    const float* noise  = (const float*)d_in[4];
    const float* fbank  = (const float*)d_in[5];

    params_kernel<<<1, 64>>>(gates, gauss, unif, fbank);
    hpass_kernel<<<dim3(Hh / 2, Nn), 192>>>(images);
    vpass_kernel<<<dim3(Hh / RY, Cc, Nn), 128>>>(noise, (float*)d_out);
}

// round 11
// speedup vs baseline: 1.0216x; 1.0216x over previous
#include <cuda_runtime.h>
#include <math.h>

#define Nn 64
#define Cc 3
#define Hh 256
#define Ww 256
#define TAP 43
#define PAD 21
#define RY 32   // rows per thread in vertical pass

struct Params {
    float M[12];      // rows 0..2 of the 4x4 color matrix (3x4: 3x3 + bias col)
    float k[TAP];     // per-image separable filter taps
    float sigma, cx, cy, half;
};

__device__ Params g_params[Nn];
// scratch between passes; float4-typed so the base is 16B-aligned for vector access
__device__ float4 g_tmp4[(Nn * Cc * Hh * Ww) / 4];   // 50.3 MB

typedef unsigned long long u64;

// packed fp32x2 FMA: acc = v * k + acc  (per-lane IEEE f32, PTX ISA sm_100+)
__device__ __forceinline__ void fma2(u64& acc, u64 v, u64 k) {
    asm("fma.rn.f32x2 %0, %1, %2, %3;" : "=l"(acc) : "l"(v), "l"(k), "l"(acc));
}

__device__ __forceinline__ void mm4(const float A[4][4], const float B[4][4], float C[4][4]) {
#pragma unroll
    for (int i = 0; i < 4; ++i)
#pragma unroll
        for (int j = 0; j < 4; ++j)
            C[i][j] = A[i][0]*B[0][j] + A[i][1]*B[1][j] + A[i][2]*B[2][j] + A[i][3]*B[3][j];
}

// one block per image; all 32 lanes run the scalar chain redundantly (SIMT),
// taps are computed lane-strided so the 64 blocks overlap all cold-miss latency.
__global__ void __launch_bounds__(32) params_kernel(const float* __restrict__ gates,
                                                    const float* __restrict__ gauss,
                                                    const float* __restrict__ unif,
                                                    const float* __restrict__ fbank) {
    int n = blockIdx.x;
    int lane = threadIdx.x;
    const float P = 1.0f;
    const float third = 1.0f / 3.0f;

    float b  = (gates[n*11+0] < P) ? gauss[n*8+0] * 0.2f : 0.0f;
    float cc = (gates[n*11+1] < P) ? exp2f(gauss[n*8+1] * 0.5f) : 1.0f;

    float T[4][4] = {{1,0,0,b},{0,1,0,b},{0,0,1,b},{0,0,0,1}};
    float S[4][4] = {{cc,0,0,0},{0,cc,0,0},{0,0,cc,0},{0,0,0,1}};
    float C1[4][4]; mm4(S, T, C1);

    float ilf = floorf(unif[n*4+0] * 2.0f);
    if (!(gates[n*11+2] < P)) ilf = 0.0f;
    float Lm[4][4];
#pragma unroll
    for (int i = 0; i < 4; ++i)
#pragma unroll
        for (int j = 0; j < 4; ++j) {
            float vvij = (i < 3 && j < 3) ? third : 0.0f;
            Lm[i][j] = ((i == j) ? 1.0f : 0.0f) - 2.0f * vvij * ilf;
        }
    float C2[4][4]; mm4(Lm, C1, C2);

    float theta = (gates[n*11+3] < P) ? (unif[n*4+1] * 2.0f - 1.0f) * 3.14159274f : 0.0f;
    float si, co;
    sincosf(theta, &si, &co);
    const float iv = 0.57735026918962576f;
    const float Kk[3][3] = {{0.0f,-iv,iv},{iv,0.0f,-iv},{-iv,iv,0.0f}};
    float R4[4][4] = {{0,0,0,0},{0,0,0,0},{0,0,0,0},{0,0,0,1}};
#pragma unroll
    for (int i = 0; i < 3; ++i)
#pragma unroll
        for (int j = 0; j < 3; ++j)
            R4[i][j] = (1.0f - co) * third + co * ((i == j) ? 1.0f : 0.0f) + si * Kk[i][j];
    float C3[4][4]; mm4(R4, C2, C3);

    float sat = (gates[n*11+4] < P) ? exp2f(gauss[n*8+2]) : 1.0f;
    float Wm[4][4];
#pragma unroll
    for (int i = 0; i < 4; ++i)
#pragma unroll
        for (int j = 0; j < 4; ++j) {
            float vvij = (i < 3 && j < 3) ? third : 0.0f;
            Wm[i][j] = vvij + (((i == j) ? 1.0f : 0.0f) - vvij) * sat;
        }
    float Cm[4][4]; mm4(Wm, C3, Cm);

    float g4[4] = {1.0f, 1.0f, 1.0f, 1.0f};
    const float ep0 = 10.0f / 13.0f, ep1 = 1.0f / 13.0f;
#pragma unroll
    for (int i = 0; i < 4; ++i) {
        float ti = (gates[n*11+5+i] < P) ? exp2f(gauss[n*8+3+i]) : 1.0f;
        float t[4] = {1.0f, 1.0f, 1.0f, 1.0f};
        t[i] = ti;
        float ss = ep0*t[0]*t[0] + ep1*t[1]*t[1] + ep1*t[2]*t[2] + ep1*t[3]*t[3];
        float inv = 1.0f / sqrtf(ss);
#pragma unroll
        for (int j = 0; j < 4; ++j) g4[j] *= t[j] * inv;
    }

    // taps lane-strided: lanes 0..31 do tp=lane, lanes 0..10 also tp=lane+32
#pragma unroll
    for (int it = 0; it < 2; ++it) {
        int tp = lane + it * 32;
        if (tp < TAP)
            g_params[n].k[tp] = g4[0]*fbank[0*TAP+tp] + g4[1]*fbank[1*TAP+tp]
                              + g4[2]*fbank[2*TAP+tp] + g4[3]*fbank[3*TAP+tp];
    }

    if (lane == 0) {
#pragma unroll
        for (int i = 0; i < 3; ++i)
#pragma unroll
            for (int j = 0; j < 4; ++j)
                g_params[n].M[i*4 + j] = Cm[i][j];
        g_params[n].sigma = (gates[n*11+9] < P) ? fabsf(gauss[n*8+7]) * 0.1f : 0.0f;
        g_params[n].cx   = unif[n*4+2];
        g_params[n].cy   = unif[n*4+3];
        g_params[n].half = (gates[n*11+10] < P) ? 0.25f : 0.0f;
    }
}

// ---- pass 1: color transform + horizontal 43-tap conv (reflect pad) ----
// block = (4-row group, n), 192 threads = 2 row-pairs x 3 channels x 32 x-groups.
// Row pairs packed as float2(y, y+1); taps register-resident; 8 outputs/thread.
__global__ void __launch_bounds__(192) hpass_kernel(const float* __restrict__ img) {
    int n = blockIdx.y;
    int tid = threadIdx.x;
    int pairId = tid / 96;            // 0..1  (rows y0+2*pairId, +1)
    int t96    = tid % 96;            // 0..95 within pair
    int y0 = blockIdx.x * 4 + pairId * 2;

    __shared__ __align__(16) float2 t2[2][3][304];  // [pair][channel][pos]
    __shared__ float2 ks2[TAP];
    __shared__ float  Ms[12];

    if (tid < 12) Ms[tid] = g_params[n].M[tid];
    if (tid >= 64 && tid < 64 + TAP) {
        float kv = g_params[n].k[tid - 64];
        ks2[tid - 64] = make_float2(kv, kv);
    }
    __syncthreads();

    const float* base = img + (size_t)n * 3 * Hh * Ww;

#pragma unroll
    for (int it = 0; it < 4; ++it) {
        int p = t96 + it * 96;
        if (p < Ww + 2*PAD) {
            int xr = p - PAD;
            xr = xr < 0 ? -xr : (xr >= Ww ? 2*Ww - 2 - xr : xr);
            float r0 = base[(0*Hh + y0    ) * Ww + xr];
            float g0 = base[(1*Hh + y0    ) * Ww + xr];
            float b0 = base[(2*Hh + y0    ) * Ww + xr];
            float r1 = base[(0*Hh + y0 + 1) * Ww + xr];
            float g1 = base[(1*Hh + y0 + 1) * Ww + xr];
            float b1 = base[(2*Hh + y0 + 1) * Ww + xr];
            t2[pairId][0][p] = make_float2(Ms[0]*r0 + Ms[1]*g0 + Ms[2] *b0 + Ms[3],
                                           Ms[0]*r1 + Ms[1]*g1 + Ms[2] *b1 + Ms[3]);
            t2[pairId][1][p] = make_float2(Ms[4]*r0 + Ms[5]*g0 + Ms[6] *b0 + Ms[7],
                                           Ms[4]*r1 + Ms[5]*g1 + Ms[6] *b1 + Ms[7]);
            t2[pairId][2][p] = make_float2(Ms[8]*r0 + Ms[9]*g0 + Ms[10]*b0 + Ms[11],
                                           Ms[8]*r1 + Ms[9]*g1 + Ms[10]*b1 + Ms[11]);
        }
    }
    __syncthreads();

    // taps -> registers (43 LDS total, then pure FFMA2 inner loop)
    u64 kr[TAP];
    {
        const u64* kk = (const u64*)ks2;
#pragma unroll
        for (int j = 0; j < TAP; ++j) kr[j] = kk[j];
    }

    int c = t96 / 32, xg = t96 % 32;          // outputs x0..x0+7, x0 = 8*xg
    const ulonglong2* tv = (const ulonglong2*)&t2[pairId][c][0];

    u64 acc[8];
#pragma unroll
    for (int i = 0; i < 8; ++i) acc[i] = 0ull;

#pragma unroll
    for (int q = 0; q < 25; ++q) {            // padded positions x0 .. x0+49
        ulonglong2 v = tv[xg*4 + q];
#pragma unroll
        for (int i = 0; i < 8; ++i) {
            int pp0 = 2*q - i;                // tap index for output x0+i
            if (pp0 >= 0 && pp0 < TAP) fma2(acc[i], v.x, kr[pp0]);
            int pp1 = 2*q + 1 - i;
            if (pp1 >= 0 && pp1 < TAP) fma2(acc[i], v.y, kr[pp1]);
        }
    }

    float* gt = (float*)g_tmp4;
    float* trow0 = gt + ((size_t)(n*3+c)*Hh + y0    ) * Ww + xg*8;
    float* trow1 = gt + ((size_t)(n*3+c)*Hh + y0 + 1) * Ww + xg*8;
#pragma unroll
    for (int h = 0; h < 2; ++h) {             // 2 float4 stores per row
        float2 e0 = *(float2*)&acc[h*4+0], e1 = *(float2*)&acc[h*4+1];
        float2 e2 = *(float2*)&acc[h*4+2], e3 = *(float2*)&acc[h*4+3];
        *((float4*)(trow0 + h*4)) = make_float4(e0.x, e1.x, e2.x, e3.x);
        *((float4*)(trow1 + h*4)) = make_float4(e0.y, e1.y, e2.y, e3.y);
    }
}

// ---- pass 2: vertical 43-tap conv (reflect pad) + noise + cutout mask ----
// block = 64 threads, each owns 2 adjacent columns (packed) x RY=32 rows.
// grid = (8 ytiles * 2 xtiles, 3, 64). Taps register-resident.
__global__ void __launch_bounds__(64) vpass_kernel(const float* __restrict__ noise,
                                                   float* __restrict__ out) {
    int n = blockIdx.z, c = blockIdx.y;
    int ytile = blockIdx.x >> 1, xt = blockIdx.x & 1;
    int y0 = ytile * RY;
    int x0 = (xt * 64 + threadIdx.x) * 2;

    __shared__ float2 ks2[TAP];
    __shared__ float  sc[4];
    if (threadIdx.x < TAP) {
        float kv = g_params[n].k[threadIdx.x];
        ks2[threadIdx.x] = make_float2(kv, kv);
    }
    if (threadIdx.x == 63) {
        sc[0] = g_params[n].sigma; sc[1] = g_params[n].cx;
        sc[2] = g_params[n].cy;    sc[3] = g_params[n].half;
    }
    __syncthreads();

    u64 kr[TAP];
    {
        const u64* kk = (const u64*)ks2;
#pragma unroll
        for (int j = 0; j < TAP; ++j) kr[j] = kk[j];
    }

    const float* base = (const float*)g_tmp4 + (size_t)(n*3+c) * Hh * Ww;

    u64 acc[RY];
#pragma unroll
    for (int r = 0; r < RY; ++r) acc[r] = 0ull;

#pragma unroll
    for (int tt = 0; tt < RY + 2*PAD; ++tt) {
        int yr = y0 + tt - PAD;
        yr = yr < 0 ? -yr : (yr >= Hh ? 2*Hh - 2 - yr : yr);
        u64 v = *(const u64*)(base + yr * Ww + x0);
#pragma unroll
        for (int r = 0; r < RY; ++r) {
            int j = tt - r;                    // compile-time in unrolled code
            if (j >= 0 && j < TAP) fma2(acc[r], v, kr[j]);
        }
    }

    float sigma = sc[0], cx = sc[1], cy = sc[2], half = sc[3];
    u64 sig2; { float2 s2 = make_float2(sigma, sigma); sig2 = *(u64*)&s2; }
    bool mx0 = fabsf((x0 + 0.5f)     * (1.0f/Ww) - cx) >= half;
    bool mx1 = fabsf((x0 + 1 + 0.5f) * (1.0f/Ww) - cx) >= half;
    const float* nb = noise + (size_t)(n*3+c) * Hh * Ww;
    float* ob = out + (size_t)(n*3+c) * Hh * Ww;
#pragma unroll
    for (int r = 0; r < RY; ++r) {
        int y = y0 + r;
        bool my = fabsf((y + 0.5f) * (1.0f/Hh) - cy) >= half;
        u64 nv = *(const u64*)(nb + y * Ww + x0);
        u64 res = acc[r];
        fma2(res, nv, sig2);                   // res = acc + noise*sigma (packed)
        float2 f = *(float2*)&res;
        float2 o;
        o.x = (mx0 || my) ? f.x : 0.0f;
        o.y = (mx1 || my) ? f.y : 0.0f;
        *((float2*)(ob + y * Ww + x0)) = o;
    }
}

extern "C" void kernel_launch(void* const* d_in, const int* in_sizes, int n_in,
                              void* d_out, int out_size) {
    const float* images = (const float*)d_in[0];
    const float* gates  = (const float*)d_in[1];
    const float* gauss  = (const float*)d_in[2];
    const float* unif   = (const float*)d_in[3];
    const float* noise  = (const float*)d_in[4];
    const float* fbank  = (const float*)d_in[5];

    params_kernel<<<Nn, 32>>>(gates, gauss, unif, fbank);
    hpass_kernel<<<dim3(Hh / 4, Nn), 192>>>(images);
    vpass_kernel<<<dim3((Hh / RY) * 2, Cc, Nn), 64>>>(noise, (float*)d_out);
}